// round 7
// baseline (speedup 1.0000x reference)
#include <cuda_runtime.h>
#include <math.h>

// Problem constants
#define Bc 64
#define Tc 128
#define Dc 1024
#define MU 8192            // B*T rows of xs

#define ROWS_PER_BLK 8

// Scratch (device globals: allocation-free per harness rules)
__device__ float g_xs[MU];
__device__ unsigned int g_done;   // zero at load; reset by last block each run

// ---------------------------------------------------------------------------
// Single fused kernel.
// Phase 1 (all 1024 blocks, 256 thr): xs[b,t] = x[b,t] . w_x, 8 rows/block,
//   1 weight float4 + 8 independent row float4 per thread (MLP=8, regs~16-ish).
// Phase 2 (elected last block): full loss.
//   loss_row(j) = log( sum_{t=j+2}^{len-1} exp(xs_t - M) ) + M - xs_{j+2}
//   (LSTM head + fc_b cancel along the softmax axis -> dead inputs.)
//   Suffix sums via warp shfl_down suffix scan; 8 warps x 8 batches.
// ---------------------------------------------------------------------------
__global__ __launch_bounds__(256, 6) void fused_kernel(const float* __restrict__ x,
                                                       const float* __restrict__ fc_w,
                                                       const int* __restrict__ mask,
                                                       float* __restrict__ out) {
    const int tid  = threadIdx.x;
    const int lane = tid & 31;
    const int warp = tid >> 5;

    // ---- Phase 1: xs for 8 rows ----
    {
        const int r0 = blockIdx.x * ROWS_PER_BLK;
        const float4* xb = (const float4*)(x + (size_t)r0 * Dc);
        const float4  w  = ((const float4*)(fc_w + 512))[tid];

        float4 a[ROWS_PER_BLK];
#pragma unroll
        for (int i = 0; i < ROWS_PER_BLK; i++)
            a[i] = xb[i * 256 + tid];          // 8 independent LDG.128

        float s[ROWS_PER_BLK];
#pragma unroll
        for (int i = 0; i < ROWS_PER_BLK; i++)
            s[i] = a[i].x * w.x + a[i].y * w.y + a[i].z * w.z + a[i].w * w.w;

#pragma unroll
        for (int off = 16; off; off >>= 1)
#pragma unroll
            for (int i = 0; i < ROWS_PER_BLK; i++)
                s[i] += __shfl_xor_sync(0xffffffffu, s[i], off);

        __shared__ float wsum[8][ROWS_PER_BLK];
        if (lane == 0) {
#pragma unroll
            for (int i = 0; i < ROWS_PER_BLK; i++) wsum[warp][i] = s[i];
        }
        __syncthreads();
        if (tid < ROWS_PER_BLK) {
            float t = 0.f;
#pragma unroll
            for (int k = 0; k < 8; k++) t += wsum[k][tid];
            g_xs[r0 + tid] = t;
        }
    }

    // ---- elect last block ----
    __shared__ unsigned int s_last;
    __threadfence();
    __syncthreads();
    if (tid == 0) s_last = atomicAdd(&g_done, 1u);
    __syncthreads();
    if (s_last != gridDim.x - 1) return;
    __threadfence();

    // ---- Phase 2: loss, 8 warps x 8 batches each ----
    __shared__ float s_tot[8];
    __shared__ float s_cnt[8];

    float acc = 0.f;
    float cntf = 0.f;

#pragma unroll
    for (int k = 0; k < 8; k++) {
        const int b = warp + k * 8;

        // len = sum(mask[b,:]) : int4 per lane
        const int4 mv = ((const int4*)(mask + b * Tc))[lane];
        int len = mv.x + mv.y + mv.z + mv.w;
#pragma unroll
        for (int off = 16; off; off >>= 1)
            len += __shfl_xor_sync(0xffffffffu, len, off);

        // xs row: 4 chunks of 32
        float v[4];
#pragma unroll
        for (int c = 0; c < 4; c++)
            v[c] = g_xs[b * Tc + c * 32 + lane];

        // per-batch max (constant shift; xs is O(1) so no overflow risk)
        float M = fmaxf(fmaxf(v[0], v[1]), fmaxf(v[2], v[3]));
#pragma unroll
        for (int off = 16; off; off >>= 1)
            M = fmaxf(M, __shfl_xor_sync(0xffffffffu, M, off));

        // masked exponentials
        float e[4];
#pragma unroll
        for (int c = 0; c < 4; c++) {
            const int t = c * 32 + lane;
            e[c] = (t < len) ? __expf(v[c] - M) : 0.f;
        }

        // suffix-sum scan, chunk 3 -> 0, carry = sum of later chunks
        float carry = 0.f;
#pragma unroll
        for (int c = 3; c >= 0; c--) {
            float ss = e[c];
#pragma unroll
            for (int off = 1; off < 32; off <<= 1) {
                float s2 = __shfl_down_sync(0xffffffffu, ss, off);
                ss += ((lane + off) < 32) ? s2 : 0.f;
            }
            ss += carry;
            const int t = c * 32 + lane;
            if (t >= 2 && t < len)
                acc += __logf(ss) + M - v[c];
            carry = __shfl_sync(0xffffffffu, ss, 0);
        }

        if (lane == 0) {
            int cnt = len - 2;
            if (cnt < 0) cnt = 0;
            cntf += (float)cnt;
        }
    }

    // warp-reduce acc (fixed order -> deterministic)
#pragma unroll
    for (int off = 16; off; off >>= 1)
        acc += __shfl_xor_sync(0xffffffffu, acc, off);

    if (lane == 0) { s_tot[warp] = acc; s_cnt[warp] = cntf; }
    __syncthreads();

    if (tid == 0) {
        float tot = 0.f, cnt = 0.f;
#pragma unroll
        for (int k = 0; k < 8; k++) { tot += s_tot[k]; cnt += s_cnt[k]; }
        out[0] = (cnt > 0.f) ? tot / cnt : 0.f;
        g_done = 0;                      // reset for next graph replay
    }
}

// ---------------------------------------------------------------------------
extern "C" void kernel_launch(void* const* d_in, const int* in_sizes, int n_in,
                              void* d_out, int out_size) {
    const float* x    = (const float*)d_in[0];
    const int*   mask = (const int*)d_in[1];
    // d_in[2..5] (W_ih, W_hh, b_ih, b_hh) and fc_b are dead: the LSTM head
    // contribution is constant along the logsumexp axis and cancels exactly.
    const float* fc_w = (const float*)d_in[6];
    float* out = (float*)d_out;

    fused_kernel<<<MU / ROWS_PER_BLK, 256>>>(x, fc_w, mask, out);
}

// round 8
// speedup vs baseline: 1.3170x; 1.3170x over previous
#include <cuda_runtime.h>
#include <math.h>

// Problem constants
#define Bc 64
#define Tc 128
#define Dc 1024
#define MU 8192            // B*T rows of xs

#define ROWS_PER_BLK 8

// Scratch (device globals: allocation-free per harness rules)
__device__ float g_xs[MU];

// ---------------------------------------------------------------------------
// xs[b,t] = x[b,t] . w_x  (w_x = fc_w[512:])
// Grid 1024, block 256; 8 rows/block; 1 weight float4 + 8 independent
// LDG.128 per thread (MLP=8) -> DRAM-latency hidden, ~LTS-cap bound.
// (R4-proven geometry: regs~16, ~3.5us.)
// ---------------------------------------------------------------------------
__global__ __launch_bounds__(256) void xs_kernel(const float* __restrict__ x,
                                                 const float* __restrict__ fc_w) {
    const int tid = threadIdx.x;
    const int r0  = blockIdx.x * ROWS_PER_BLK;
    const float4* xb = (const float4*)(x + (size_t)r0 * Dc);
    const float4  w  = ((const float4*)(fc_w + 512))[tid];

    float4 a[ROWS_PER_BLK];
#pragma unroll
    for (int i = 0; i < ROWS_PER_BLK; i++)
        a[i] = xb[i * 256 + tid];             // 8 independent LDG.128 in flight

    float s[ROWS_PER_BLK];
#pragma unroll
    for (int i = 0; i < ROWS_PER_BLK; i++)
        s[i] = a[i].x * w.x + a[i].y * w.y + a[i].z * w.z + a[i].w * w.w;

#pragma unroll
    for (int off = 16; off; off >>= 1)
#pragma unroll
        for (int i = 0; i < ROWS_PER_BLK; i++)
            s[i] += __shfl_xor_sync(0xffffffffu, s[i], off);

    __shared__ float wsum[8][ROWS_PER_BLK];
    const int lane = tid & 31, warp = tid >> 5;
    if (lane == 0) {
#pragma unroll
        for (int i = 0; i < ROWS_PER_BLK; i++) wsum[warp][i] = s[i];
    }
    __syncthreads();
    if (tid < ROWS_PER_BLK) {
        float t = 0.f;
#pragma unroll
        for (int k = 0; k < 8; k++) t += wsum[k][tid];
        g_xs[r0 + tid] = t;
    }
}

// ---------------------------------------------------------------------------
// Loss: ONE block, 1024 threads, 32 warps x 2 batches each.
//   loss_row(j) = log( sum_{t=j+2}^{len-1} exp(xs_t - M) ) + M - xs_{j+2}
// with M = per-batch max (constant shift). Suffix sums by warp shfl_down
// suffix scan (pure FADD chain), chunk 3 -> 0 with carry.
// (LSTM head + fc_b cancel along the softmax axis -> dead inputs.)
// Fixed-order final reduction in the same block -> deterministic, no atomics.
// ---------------------------------------------------------------------------
__global__ __launch_bounds__(1024) void loss_kernel(const int* __restrict__ mask,
                                                    float* __restrict__ out) {
    const int tid  = threadIdx.x;
    const int lane = tid & 31;
    const int warp = tid >> 5;

    __shared__ float s_tot[32];
    __shared__ float s_cnt[32];

    float acc = 0.f;
    float cntf = 0.f;

#pragma unroll
    for (int half = 0; half < 2; half++) {
        const int b = warp + half * 32;

        // len = sum(mask[b,:]) : int4 per lane
        const int4 mv = ((const int4*)(mask + b * Tc))[lane];
        int len = mv.x + mv.y + mv.z + mv.w;
#pragma unroll
        for (int off = 16; off; off >>= 1)
            len += __shfl_xor_sync(0xffffffffu, len, off);

        // xs row: 4 chunks of 32
        float v[4];
#pragma unroll
        for (int c = 0; c < 4; c++)
            v[c] = g_xs[b * Tc + c * 32 + lane];

        // per-batch max (constant shift; xs is O(1) so no overflow risk)
        float M = fmaxf(fmaxf(v[0], v[1]), fmaxf(v[2], v[3]));
#pragma unroll
        for (int off = 16; off; off >>= 1)
            M = fmaxf(M, __shfl_xor_sync(0xffffffffu, M, off));

        // masked exponentials
        float e[4];
#pragma unroll
        for (int c = 0; c < 4; c++) {
            const int t = c * 32 + lane;
            e[c] = (t < len) ? __expf(v[c] - M) : 0.f;
        }

        // suffix-sum scan, chunk 3 -> 0, carry = sum of later chunks
        float carry = 0.f;
#pragma unroll
        for (int c = 3; c >= 0; c--) {
            float ss = e[c];
#pragma unroll
            for (int off = 1; off < 32; off <<= 1) {
                float s2 = __shfl_down_sync(0xffffffffu, ss, off);
                ss += ((lane + off) < 32) ? s2 : 0.f;
            }
            ss += carry;
            const int t = c * 32 + lane;
            if (t >= 2 && t < len)
                acc += __logf(ss) + M - v[c];
            carry = __shfl_sync(0xffffffffu, ss, 0);
        }

        if (lane == 0) {
            int cnt = len - 2;
            if (cnt < 0) cnt = 0;
            cntf += (float)cnt;
        }
    }

    // warp-reduce acc (fixed order -> deterministic)
#pragma unroll
    for (int off = 16; off; off >>= 1)
        acc += __shfl_xor_sync(0xffffffffu, acc, off);

    if (lane == 0) { s_tot[warp] = acc; s_cnt[warp] = cntf; }
    __syncthreads();

    if (tid == 0) {
        float tot = 0.f, cnt = 0.f;
#pragma unroll
        for (int k = 0; k < 32; k++) { tot += s_tot[k]; cnt += s_cnt[k]; }
        out[0] = (cnt > 0.f) ? tot / cnt : 0.f;
    }
}

// ---------------------------------------------------------------------------
extern "C" void kernel_launch(void* const* d_in, const int* in_sizes, int n_in,
                              void* d_out, int out_size) {
    const float* x    = (const float*)d_in[0];
    const int*   mask = (const int*)d_in[1];
    // d_in[2..5] (W_ih, W_hh, b_ih, b_hh) and fc_b are dead: the LSTM head
    // contribution is constant along the logsumexp axis and cancels exactly.
    const float* fc_w = (const float*)d_in[6];
    float* out = (float*)d_out;

    xs_kernel<<<MU / ROWS_PER_BLK, 256>>>(x, fc_w);
    loss_kernel<<<1, 1024>>>(mask, out);
}